// round 5
// baseline (speedup 1.0000x reference)
#include <cuda_runtime.h>
#include <math.h>

// Problem dims (fixed by the reference)
#define BATCH   2
#define SEQ     2048
#define EMB     1024
#define NHEAD   16
#define HDIM    64
#define MROWS   (BATCH * SEQ)   // 4096
#define NQKV    (3 * EMB)       // 3072

// Scratch (no cudaMalloc allowed): q/k/v in [B,H,T,hd], y in [B,T,C]
__device__ float g_q[BATCH * NHEAD * SEQ * HDIM];
__device__ float g_k[BATCH * NHEAD * SEQ * HDIM];
__device__ float g_v[BATCH * NHEAD * SEQ * HDIM];
__device__ float g_y[BATCH * SEQ * EMB];

// ---------------------------------------------------------------------------
// GEMM1: qkv = x @ W_attn + b_attn, scattered into g_q/g_k/g_v [B,H,T,hd]
// 128x128 block tile, BK=16, 256 threads, 8x8 per thread.
// ---------------------------------------------------------------------------
__global__ void __launch_bounds__(256) gemm_qkv_kernel(
    const float* __restrict__ A,      // x [MROWS, EMB]
    const float* __restrict__ W,      // W_attn [EMB, NQKV]
    const float* __restrict__ bias)   // b_attn [NQKV]
{
    __shared__ float As[16][128];
    __shared__ float Bs[16][128];
    const int tid = threadIdx.x;
    const int tx = tid & 15;
    const int ty = tid >> 4;
    const int brow = blockIdx.y * 128;
    const int bcol = blockIdx.x * 128;

    float acc[8][8];
#pragma unroll
    for (int i = 0; i < 8; i++)
#pragma unroll
        for (int j = 0; j < 8; j++) acc[i][j] = 0.f;

    for (int k0 = 0; k0 < EMB; k0 += 16) {
#pragma unroll
        for (int i = 0; i < 2; i++) {
            int id = tid + i * 256;
            int r  = id >> 2;            // 0..127
            int c4 = (id & 3) * 4;       // 0,4,8,12
            float4 v = *reinterpret_cast<const float4*>(
                &A[(size_t)(brow + r) * EMB + k0 + c4]);
            As[c4 + 0][r] = v.x;
            As[c4 + 1][r] = v.y;
            As[c4 + 2][r] = v.z;
            As[c4 + 3][r] = v.w;
        }
#pragma unroll
        for (int i = 0; i < 2; i++) {
            int id = tid + i * 256;
            int r  = id >> 5;            // 0..15
            int c4 = (id & 31) * 4;      // 0..124
            *reinterpret_cast<float4*>(&Bs[r][c4]) =
                *reinterpret_cast<const float4*>(
                    &W[(size_t)(k0 + r) * NQKV + bcol + c4]);
        }
        __syncthreads();
#pragma unroll
        for (int kk = 0; kk < 16; kk++) {
            float a[8], b[8];
#pragma unroll
            for (int i = 0; i < 8; i++) a[i] = As[kk][ty * 8 + i];
#pragma unroll
            for (int j = 0; j < 8; j++) b[j] = Bs[kk][tx * 8 + j];
#pragma unroll
            for (int i = 0; i < 8; i++)
#pragma unroll
                for (int j = 0; j < 8; j++)
                    acc[i][j] = fmaf(a[i], b[j], acc[i][j]);
        }
        __syncthreads();
    }

    // Epilogue: part (q/k/v) is uniform per block since 128 | 1024.
    const int part = bcol / EMB;
    float* dst = (part == 0) ? g_q : ((part == 1) ? g_k : g_v);
#pragma unroll
    for (int i = 0; i < 8; i++) {
        int m  = brow + ty * 8 + i;
        int bb = m / SEQ;
        int t  = m % SEQ;
#pragma unroll
        for (int j = 0; j < 8; j++) {
            int n   = bcol + tx * 8 + j;
            int cin = n % EMB;
            int h   = cin / HDIM;
            int d   = cin % HDIM;
            dst[(((size_t)(bb * NHEAD + h)) * SEQ + t) * HDIM + d] =
                acc[i][j] + bias[n];
        }
    }
}

// ---------------------------------------------------------------------------
// GEMM2: out = y @ W_proj + b_proj   (y read from g_y [MROWS, EMB])
// ---------------------------------------------------------------------------
__global__ void __launch_bounds__(256) gemm_proj_kernel(
    const float* __restrict__ W,      // W_proj [EMB, EMB]
    const float* __restrict__ bias,   // b_proj [EMB]
    float* __restrict__ out)          // [MROWS, EMB]
{
    __shared__ float As[16][128];
    __shared__ float Bs[16][128];
    const int tid = threadIdx.x;
    const int tx = tid & 15;
    const int ty = tid >> 4;
    const int brow = blockIdx.y * 128;
    const int bcol = blockIdx.x * 128;

    float acc[8][8];
#pragma unroll
    for (int i = 0; i < 8; i++)
#pragma unroll
        for (int j = 0; j < 8; j++) acc[i][j] = 0.f;

    for (int k0 = 0; k0 < EMB; k0 += 16) {
#pragma unroll
        for (int i = 0; i < 2; i++) {
            int id = tid + i * 256;
            int r  = id >> 2;
            int c4 = (id & 3) * 4;
            float4 v = *reinterpret_cast<const float4*>(
                &g_y[(size_t)(brow + r) * EMB + k0 + c4]);
            As[c4 + 0][r] = v.x;
            As[c4 + 1][r] = v.y;
            As[c4 + 2][r] = v.z;
            As[c4 + 3][r] = v.w;
        }
#pragma unroll
        for (int i = 0; i < 2; i++) {
            int id = tid + i * 256;
            int r  = id >> 5;
            int c4 = (id & 31) * 4;
            *reinterpret_cast<float4*>(&Bs[r][c4]) =
                *reinterpret_cast<const float4*>(
                    &W[(size_t)(k0 + r) * EMB + bcol + c4]);
        }
        __syncthreads();
#pragma unroll
        for (int kk = 0; kk < 16; kk++) {
            float a[8], b[8];
#pragma unroll
            for (int i = 0; i < 8; i++) a[i] = As[kk][ty * 8 + i];
#pragma unroll
            for (int j = 0; j < 8; j++) b[j] = Bs[kk][tx * 8 + j];
#pragma unroll
            for (int i = 0; i < 8; i++)
#pragma unroll
                for (int j = 0; j < 8; j++)
                    acc[i][j] = fmaf(a[i], b[j], acc[i][j]);
        }
        __syncthreads();
    }

#pragma unroll
    for (int i = 0; i < 8; i++) {
        int m = brow + ty * 8 + i;
#pragma unroll
        for (int j = 0; j < 8; j++) {
            int n = bcol + tx * 8 + j;
            out[(size_t)m * EMB + n] = acc[i][j] + bias[n];
        }
    }
}

// ---------------------------------------------------------------------------
// Fused causal LIF attention, two passes.
// Block: 32 query rows x 8 lanes/row (256 threads). K/V tiles 64x64 in SMEM.
// Pass 1: online softmax stats (m, l). Pass 2: p = exp(s-m)/l,
// fire = sigmoid(st*(p-thr)), lif = lk + fire*(1-lk), mod = p*lif,
// acc += mod*V, smod += mod; y = acc/(smod+1e-8). Writes g_y in [B,T,C].
//
// SAFETY: the inner key loop bound is WARP-UNIFORM (computed from the warp's
// max query row). Causality is enforced by predication (masked keys get
// s = -1e30 -> exp underflows to 0). So every __shfl_xor_sync is executed by
// all lanes of its mask on every iteration — no divergence hazard.
// ---------------------------------------------------------------------------
__global__ void __launch_bounds__(256) lif_attn_kernel(
    const float* __restrict__ thr_p,
    const float* __restrict__ leak_p,
    const float* __restrict__ steep_p)
{
    __shared__ float Ks[64][64];
    __shared__ float Vs[64][64];

    const int b  = blockIdx.z;
    const int h  = blockIdx.y;
    const int qt = blockIdx.x;
    const int tid = threadIdx.x;
    const int row = tid >> 3;      // 0..31 query row within block
    const int sub = tid & 7;       // 0..7 lane within row-group
    const int qg  = qt * 32 + row; // this thread's query index
    const int wq  = tid >> 5;      // warp id (rows 4*wq .. 4*wq+3)
    const int qg_wmax = qt * 32 + wq * 4 + 3;  // warp's max query index

    // 8-lane group mask within this warp (lanes {g*8 .. g*8+7})
    const unsigned gmask = 0xFFu << ((tid & 31) & ~7);

    // Per-head LIF params (robust softplus)
    const float sx  = steep_p[h];
    const float st  = fmaxf(sx, 0.f) + log1pf(__expf(-fabsf(sx)));
    const float lk  = 1.f / (1.f + __expf(-leak_p[h]));
    const float thr = fabsf(thr_p[h]) * 0.1f;

    const float* Kbase = g_k + ((size_t)(b * NHEAD + h)) * SEQ * HDIM;
    const float* Vbase = g_v + ((size_t)(b * NHEAD + h)) * SEQ * HDIM;
    const float* Qp    = g_q + (((size_t)(b * NHEAD + h)) * SEQ + qg) * HDIM + sub * 8;

    float q[8];
    {
        float4 q0 = *reinterpret_cast<const float4*>(Qp);
        float4 q1 = *reinterpret_cast<const float4*>(Qp + 4);
        const float scale = 0.125f;  // 1/sqrt(64)
        q[0] = q0.x * scale; q[1] = q0.y * scale;
        q[2] = q0.z * scale; q[3] = q0.w * scale;
        q[4] = q1.x * scale; q[5] = q1.y * scale;
        q[6] = q1.z * scale; q[7] = q1.w * scale;
    }

    const int nkt = qt / 2 + 1;    // k-tiles covering keys 0..(qt*32+31)

    // ---------------- Pass 1: softmax stats ----------------
    float m = -1e30f, l = 0.f;
    for (int kt = 0; kt < nkt; kt++) {
#pragma unroll
        for (int i = 0; i < 4; i++) {
            int id4 = tid + i * 256;
            int r   = id4 >> 4;
            int c4  = (id4 & 15) * 4;
            *reinterpret_cast<float4*>(&Ks[r][c4]) =
                *reinterpret_cast<const float4*>(
                    &Kbase[(size_t)(kt * 64 + r) * HDIM + c4]);
        }
        __syncthreads();
        // Warp-uniform trip count; per-row causal masking by predication.
        const int kmaxw = min(64, qg_wmax - kt * 64 + 1);  // >= 1, same for all 32 lanes
        const int kofs  = kt * 64;
#pragma unroll 4
        for (int k = 0; k < kmaxw; k++) {
            const float* kr = &Ks[k][sub * 8];
            float s = q[0] * kr[0];
#pragma unroll
            for (int j = 1; j < 8; j++) s = fmaf(q[j], kr[j], s);
            s += __shfl_xor_sync(gmask, s, 1);
            s += __shfl_xor_sync(gmask, s, 2);
            s += __shfl_xor_sync(gmask, s, 4);
            if (kofs + k > qg) s = -1e30f;   // causal mask (exp -> 0)
            float mn = fmaxf(m, s);
            l = l * __expf(m - mn) + __expf(s - mn);
            m = mn;
        }
        __syncthreads();
    }
    const float linv = 1.f / l;   // l >= 1 (diagonal key always present)

    // ---------------- Pass 2: LIF modulation + PV ----------------
    float acc[8];
#pragma unroll
    for (int j = 0; j < 8; j++) acc[j] = 0.f;
    float smod = 0.f;

    for (int kt = 0; kt < nkt; kt++) {
#pragma unroll
        for (int i = 0; i < 4; i++) {
            int id4 = tid + i * 256;
            int r   = id4 >> 4;
            int c4  = (id4 & 15) * 4;
            *reinterpret_cast<float4*>(&Ks[r][c4]) =
                *reinterpret_cast<const float4*>(
                    &Kbase[(size_t)(kt * 64 + r) * HDIM + c4]);
            *reinterpret_cast<float4*>(&Vs[r][c4]) =
                *reinterpret_cast<const float4*>(
                    &Vbase[(size_t)(kt * 64 + r) * HDIM + c4]);
        }
        __syncthreads();
        const int kmaxw = min(64, qg_wmax - kt * 64 + 1);
        const int kofs  = kt * 64;
#pragma unroll 4
        for (int k = 0; k < kmaxw; k++) {
            const float* kr = &Ks[k][sub * 8];
            float s = q[0] * kr[0];
#pragma unroll
            for (int j = 1; j < 8; j++) s = fmaf(q[j], kr[j], s);
            s += __shfl_xor_sync(gmask, s, 1);
            s += __shfl_xor_sync(gmask, s, 2);
            s += __shfl_xor_sync(gmask, s, 4);
            if (kofs + k > qg) s = -1e30f;   // causal mask (p -> 0, mo -> 0)
            float p    = __expf(s - m) * linv;
            float fire = 1.f / (1.f + __expf(-st * (p - thr)));
            float w    = lk + fire * (1.f - lk);
            float mo   = p * w;
            smod += mo;
            const float* vr = &Vs[k][sub * 8];
#pragma unroll
            for (int j = 0; j < 8; j++) acc[j] = fmaf(mo, vr[j], acc[j]);
        }
        __syncthreads();
    }

    const float dn = 1.f / (smod + 1e-8f);
    float* yo = g_y + ((size_t)(b * SEQ + qg)) * EMB + h * HDIM + sub * 8;
    float4 o0 = make_float4(acc[0] * dn, acc[1] * dn, acc[2] * dn, acc[3] * dn);
    float4 o1 = make_float4(acc[4] * dn, acc[5] * dn, acc[6] * dn, acc[7] * dn);
    *reinterpret_cast<float4*>(yo)     = o0;
    *reinterpret_cast<float4*>(yo + 4) = o1;
}

// ---------------------------------------------------------------------------
extern "C" void kernel_launch(void* const* d_in, const int* in_sizes, int n_in,
                              void* d_out, int out_size)
{
    const float* x      = (const float*)d_in[0];
    const float* W_attn = (const float*)d_in[1];
    const float* b_attn = (const float*)d_in[2];
    const float* W_proj = (const float*)d_in[3];
    const float* b_proj = (const float*)d_in[4];
    const float* thr    = (const float*)d_in[5];
    const float* leak   = (const float*)d_in[6];
    const float* steep  = (const float*)d_in[7];
    float* out = (float*)d_out;

    gemm_qkv_kernel<<<dim3(NQKV / 128, MROWS / 128), 256>>>(x, W_attn, b_attn);
    lif_attn_kernel<<<dim3(SEQ / 32, NHEAD, BATCH), 256>>>(thr, leak, steep);
    gemm_proj_kernel<<<dim3(EMB / 128, MROWS / 128), 256>>>(W_proj, b_proj, out);
}

// round 6
// speedup vs baseline: 2.4513x; 2.4513x over previous
#include <cuda_runtime.h>
#include <math.h>

// Problem dims (fixed by the reference)
#define BATCH   2
#define SEQ     2048
#define EMB     1024
#define NHEAD   16
#define HDIM    64
#define MROWS   (BATCH * SEQ)   // 4096
#define NQKV    (3 * EMB)       // 3072

// Scratch (no cudaMalloc allowed): q/k/v in [B,H,T,hd], y in [B,T,C]
__device__ float g_q[BATCH * NHEAD * SEQ * HDIM];
__device__ float g_k[BATCH * NHEAD * SEQ * HDIM];
__device__ float g_v[BATCH * NHEAD * SEQ * HDIM];
__device__ float g_y[BATCH * SEQ * EMB];

// ---------------------------------------------------------------------------
// GEMM1: qkv = x @ W_attn + b_attn, scattered into g_q/g_k/g_v [B,H,T,hd]
// ---------------------------------------------------------------------------
__global__ void __launch_bounds__(256) gemm_qkv_kernel(
    const float* __restrict__ A,      // x [MROWS, EMB]
    const float* __restrict__ W,      // W_attn [EMB, NQKV]
    const float* __restrict__ bias)   // b_attn [NQKV]
{
    __shared__ float As[16][128];
    __shared__ float Bs[16][128];
    const int tid = threadIdx.x;
    const int tx = tid & 15;
    const int ty = tid >> 4;
    const int brow = blockIdx.y * 128;
    const int bcol = blockIdx.x * 128;

    float acc[8][8];
#pragma unroll
    for (int i = 0; i < 8; i++)
#pragma unroll
        for (int j = 0; j < 8; j++) acc[i][j] = 0.f;

    for (int k0 = 0; k0 < EMB; k0 += 16) {
#pragma unroll
        for (int i = 0; i < 2; i++) {
            int id = tid + i * 256;
            int r  = id >> 2;
            int c4 = (id & 3) * 4;
            float4 v = *reinterpret_cast<const float4*>(
                &A[(size_t)(brow + r) * EMB + k0 + c4]);
            As[c4 + 0][r] = v.x;
            As[c4 + 1][r] = v.y;
            As[c4 + 2][r] = v.z;
            As[c4 + 3][r] = v.w;
        }
#pragma unroll
        for (int i = 0; i < 2; i++) {
            int id = tid + i * 256;
            int r  = id >> 5;
            int c4 = (id & 31) * 4;
            *reinterpret_cast<float4*>(&Bs[r][c4]) =
                *reinterpret_cast<const float4*>(
                    &W[(size_t)(k0 + r) * NQKV + bcol + c4]);
        }
        __syncthreads();
#pragma unroll
        for (int kk = 0; kk < 16; kk++) {
            float a[8], b[8];
#pragma unroll
            for (int i = 0; i < 8; i++) a[i] = As[kk][ty * 8 + i];
#pragma unroll
            for (int j = 0; j < 8; j++) b[j] = Bs[kk][tx * 8 + j];
#pragma unroll
            for (int i = 0; i < 8; i++)
#pragma unroll
                for (int j = 0; j < 8; j++)
                    acc[i][j] = fmaf(a[i], b[j], acc[i][j]);
        }
        __syncthreads();
    }

    const int part = bcol / EMB;
    float* dst = (part == 0) ? g_q : ((part == 1) ? g_k : g_v);
#pragma unroll
    for (int i = 0; i < 8; i++) {
        int m  = brow + ty * 8 + i;
        int bb = m / SEQ;
        int t  = m % SEQ;
#pragma unroll
        for (int j = 0; j < 8; j++) {
            int n   = bcol + tx * 8 + j;
            int cin = n % EMB;
            int h   = cin / HDIM;
            int d   = cin % HDIM;
            dst[(((size_t)(bb * NHEAD + h)) * SEQ + t) * HDIM + d] =
                acc[i][j] + bias[n];
        }
    }
}

// ---------------------------------------------------------------------------
// GEMM2: out = y @ W_proj + b_proj   (y read from g_y [MROWS, EMB])
// ---------------------------------------------------------------------------
__global__ void __launch_bounds__(256) gemm_proj_kernel(
    const float* __restrict__ W,
    const float* __restrict__ bias,
    float* __restrict__ out)
{
    __shared__ float As[16][128];
    __shared__ float Bs[16][128];
    const int tid = threadIdx.x;
    const int tx = tid & 15;
    const int ty = tid >> 4;
    const int brow = blockIdx.y * 128;
    const int bcol = blockIdx.x * 128;

    float acc[8][8];
#pragma unroll
    for (int i = 0; i < 8; i++)
#pragma unroll
        for (int j = 0; j < 8; j++) acc[i][j] = 0.f;

    for (int k0 = 0; k0 < EMB; k0 += 16) {
#pragma unroll
        for (int i = 0; i < 2; i++) {
            int id = tid + i * 256;
            int r  = id >> 2;
            int c4 = (id & 3) * 4;
            float4 v = *reinterpret_cast<const float4*>(
                &g_y[(size_t)(brow + r) * EMB + k0 + c4]);
            As[c4 + 0][r] = v.x;
            As[c4 + 1][r] = v.y;
            As[c4 + 2][r] = v.z;
            As[c4 + 3][r] = v.w;
        }
#pragma unroll
        for (int i = 0; i < 2; i++) {
            int id = tid + i * 256;
            int r  = id >> 5;
            int c4 = (id & 31) * 4;
            *reinterpret_cast<float4*>(&Bs[r][c4]) =
                *reinterpret_cast<const float4*>(
                    &W[(size_t)(k0 + r) * EMB + bcol + c4]);
        }
        __syncthreads();
#pragma unroll
        for (int kk = 0; kk < 16; kk++) {
            float a[8], b[8];
#pragma unroll
            for (int i = 0; i < 8; i++) a[i] = As[kk][ty * 8 + i];
#pragma unroll
            for (int j = 0; j < 8; j++) b[j] = Bs[kk][tx * 8 + j];
#pragma unroll
            for (int i = 0; i < 8; i++)
#pragma unroll
                for (int j = 0; j < 8; j++)
                    acc[i][j] = fmaf(a[i], b[j], acc[i][j]);
        }
        __syncthreads();
    }

#pragma unroll
    for (int i = 0; i < 8; i++) {
        int m = brow + ty * 8 + i;
#pragma unroll
        for (int j = 0; j < 8; j++) {
            int n = bcol + tx * 8 + j;
            out[(size_t)m * EMB + n] = acc[i][j] + bias[n];
        }
    }
}

// ---------------------------------------------------------------------------
// Fused causal LIF attention, register-tiled GEMM formulation.
// Block = 64 queries of one (b,h). 256 threads as 16x16; each thread owns a
// 4x4 tile of the 64x64 score tile (QK pass) and a 4x4 tile of the 64x64
// output (PV pass). All loop bounds are BLOCK-UNIFORM (tile count qt+1);
// causality handled by predication on the diagonal tile only. Shuffles are
// executed by all lanes on every iteration -> no divergence hazard.
//
// SMEM (exactly 48KB):
//   Qs[d][r]  : Q^T, pre-scaled by 1/sqrt(hd), loaded once
//   KsU[.][.] : per tile, K^T [d][c] during QK; then mod [r][c] during PV
//   Vs[c][d]  : V tile, row-major
// ---------------------------------------------------------------------------
__global__ void __launch_bounds__(256) lif_attn_kernel(
    const float* __restrict__ thr_p,
    const float* __restrict__ leak_p,
    const float* __restrict__ steep_p)
{
    __shared__ float Qs [64][64];
    __shared__ float KsU[64][64];
    __shared__ float Vs [64][64];

    const int b   = blockIdx.z;
    const int h   = blockIdx.y;
    const int qt  = (gridDim.x - 1) - blockIdx.x;  // heavy blocks first
    const int tid = threadIdx.x;
    const int tx  = tid & 15;
    const int ty  = tid >> 4;

    // Per-head LIF params (robust softplus)
    const float sx  = steep_p[h];
    const float st  = fmaxf(sx, 0.f) + log1pf(__expf(-fabsf(sx)));
    const float lk  = 1.f / (1.f + __expf(-leak_p[h]));
    const float thr = fabsf(thr_p[h]) * 0.1f;

    const size_t bh = (size_t)(b * NHEAD + h) * SEQ * HDIM;
    const float* Kb = g_k + bh;
    const float* Vb = g_v + bh;
    const float* Qb = g_q + bh + (size_t)qt * 64 * HDIM;

    // Load Q transposed + scaled: Qs[d][r] = Q[r][d] / 8
    // Mapping: lanes span rows (conflict-free SMEM stores).
#pragma unroll
    for (int i = 0; i < 4; i++) {
        int id = tid + i * 256;
        int r  = id & 63;
        int c4 = (id >> 6) * 4;
        float4 v = *reinterpret_cast<const float4*>(&Qb[r * HDIM + c4]);
        Qs[c4 + 0][r] = v.x * 0.125f;
        Qs[c4 + 1][r] = v.y * 0.125f;
        Qs[c4 + 2][r] = v.z * 0.125f;
        Qs[c4 + 3][r] = v.w * 0.125f;
    }

    float m[4], l[4];
#pragma unroll
    for (int i = 0; i < 4; i++) { m[i] = -1e30f; l[i] = 0.f; }

    const int nkt = qt + 1;

    // ================= Pass 1: softmax stats =================
    for (int kt = 0; kt < nkt; kt++) {
        __syncthreads();   // KsU readers done (and Q stores visible on kt=0)
#pragma unroll
        for (int i = 0; i < 4; i++) {
            int id = tid + i * 256;
            int r  = id & 63;
            int c4 = (id >> 6) * 4;
            float4 v = *reinterpret_cast<const float4*>(
                &Kb[(size_t)(kt * 64 + r) * HDIM + c4]);
            KsU[c4 + 0][r] = v.x;
            KsU[c4 + 1][r] = v.y;
            KsU[c4 + 2][r] = v.z;
            KsU[c4 + 3][r] = v.w;
        }
        __syncthreads();

        float s[4][4];
#pragma unroll
        for (int i = 0; i < 4; i++)
#pragma unroll
            for (int j = 0; j < 4; j++) s[i][j] = 0.f;

#pragma unroll 16
        for (int d = 0; d < 64; d++) {
            float4 a = *reinterpret_cast<const float4*>(&Qs[d][ty * 4]);
            float4 bb = *reinterpret_cast<const float4*>(&KsU[d][tx * 4]);
            float av[4] = {a.x, a.y, a.z, a.w};
            float bv[4] = {bb.x, bb.y, bb.z, bb.w};
#pragma unroll
            for (int i = 0; i < 4; i++)
#pragma unroll
                for (int j = 0; j < 4; j++)
                    s[i][j] = fmaf(av[i], bv[j], s[i][j]);
        }

        if (kt == qt) {  // diagonal tile: causal mask by predication
#pragma unroll
            for (int i = 0; i < 4; i++)
#pragma unroll
                for (int j = 0; j < 4; j++)
                    if (tx * 4 + j > ty * 4 + i) s[i][j] = -1e30f;
        }

        // Online (m, l) per row: reduce across the 16 tx lanes
#pragma unroll
        for (int i = 0; i < 4; i++) {
            float tm = fmaxf(fmaxf(s[i][0], s[i][1]), fmaxf(s[i][2], s[i][3]));
            tm = fmaxf(tm, __shfl_xor_sync(0xffffffffu, tm, 1));
            tm = fmaxf(tm, __shfl_xor_sync(0xffffffffu, tm, 2));
            tm = fmaxf(tm, __shfl_xor_sync(0xffffffffu, tm, 4));
            tm = fmaxf(tm, __shfl_xor_sync(0xffffffffu, tm, 8));
            float mn = fmaxf(m[i], tm);
            float e = __expf(s[i][0] - mn) + __expf(s[i][1] - mn)
                    + __expf(s[i][2] - mn) + __expf(s[i][3] - mn);
            e += __shfl_xor_sync(0xffffffffu, e, 1);
            e += __shfl_xor_sync(0xffffffffu, e, 2);
            e += __shfl_xor_sync(0xffffffffu, e, 4);
            e += __shfl_xor_sync(0xffffffffu, e, 8);
            l[i] = l[i] * __expf(m[i] - mn) + e;
            m[i] = mn;
        }
    }

    float linv[4];
#pragma unroll
    for (int i = 0; i < 4; i++) linv[i] = 1.f / l[i];  // l >= 1 always

    // ================= Pass 2: LIF modulation + PV =================
    float o[4][4];
#pragma unroll
    for (int i = 0; i < 4; i++)
#pragma unroll
        for (int j = 0; j < 4; j++) o[i][j] = 0.f;
    float smod[4] = {0.f, 0.f, 0.f, 0.f};

    for (int kt = 0; kt < nkt; kt++) {
        __syncthreads();   // previous PV readers of KsU/Vs done
#pragma unroll
        for (int i = 0; i < 4; i++) {
            int id = tid + i * 256;
            int r  = id & 63;
            int c4 = (id >> 6) * 4;
            float4 v = *reinterpret_cast<const float4*>(
                &Kb[(size_t)(kt * 64 + r) * HDIM + c4]);
            KsU[c4 + 0][r] = v.x;
            KsU[c4 + 1][r] = v.y;
            KsU[c4 + 2][r] = v.z;
            KsU[c4 + 3][r] = v.w;
        }
#pragma unroll
        for (int i = 0; i < 4; i++) {
            int id = tid + i * 256;
            int r  = id >> 4;
            int c4 = (id & 15) * 4;
            *reinterpret_cast<float4*>(&Vs[r][c4]) =
                *reinterpret_cast<const float4*>(
                    &Vb[(size_t)(kt * 64 + r) * HDIM + c4]);
        }
        __syncthreads();

        float s[4][4];
#pragma unroll
        for (int i = 0; i < 4; i++)
#pragma unroll
            for (int j = 0; j < 4; j++) s[i][j] = 0.f;

#pragma unroll 16
        for (int d = 0; d < 64; d++) {
            float4 a = *reinterpret_cast<const float4*>(&Qs[d][ty * 4]);
            float4 bb = *reinterpret_cast<const float4*>(&KsU[d][tx * 4]);
            float av[4] = {a.x, a.y, a.z, a.w};
            float bv[4] = {bb.x, bb.y, bb.z, bb.w};
#pragma unroll
            for (int i = 0; i < 4; i++)
#pragma unroll
                for (int j = 0; j < 4; j++)
                    s[i][j] = fmaf(av[i], bv[j], s[i][j]);
        }

        if (kt == qt) {
#pragma unroll
            for (int i = 0; i < 4; i++)
#pragma unroll
                for (int j = 0; j < 4; j++)
                    if (tx * 4 + j > ty * 4 + i) s[i][j] = -1e30f;
        }

        __syncthreads();   // everyone done reading KsU before overwrite as mod

        // mod = p * (lk + fire*(1-lk)); store [r][c] into KsU
#pragma unroll
        for (int i = 0; i < 4; i++) {
            float mo[4];
#pragma unroll
            for (int j = 0; j < 4; j++) {
                float p    = __expf(s[i][j] - m[i]) * linv[i];
                float fire = 1.f / (1.f + __expf(-st * (p - thr)));
                float w    = lk + fire * (1.f - lk);
                mo[j]      = p * w;
                smod[i]   += mo[j];
            }
            *reinterpret_cast<float4*>(&KsU[ty * 4 + i][tx * 4]) =
                make_float4(mo[0], mo[1], mo[2], mo[3]);
        }
        __syncthreads();

        // PV: o[r][d4] += sum_c mod[r][c] * V[c][d4]
#pragma unroll 8
        for (int c = 0; c < 64; c++) {
            float4 bv = *reinterpret_cast<const float4*>(&Vs[c][tx * 4]);
            float a0 = KsU[ty * 4 + 0][c];
            float a1 = KsU[ty * 4 + 1][c];
            float a2 = KsU[ty * 4 + 2][c];
            float a3 = KsU[ty * 4 + 3][c];
            o[0][0] = fmaf(a0, bv.x, o[0][0]); o[0][1] = fmaf(a0, bv.y, o[0][1]);
            o[0][2] = fmaf(a0, bv.z, o[0][2]); o[0][3] = fmaf(a0, bv.w, o[0][3]);
            o[1][0] = fmaf(a1, bv.x, o[1][0]); o[1][1] = fmaf(a1, bv.y, o[1][1]);
            o[1][2] = fmaf(a1, bv.z, o[1][2]); o[1][3] = fmaf(a1, bv.w, o[1][3]);
            o[2][0] = fmaf(a2, bv.x, o[2][0]); o[2][1] = fmaf(a2, bv.y, o[2][1]);
            o[2][2] = fmaf(a2, bv.z, o[2][2]); o[2][3] = fmaf(a2, bv.w, o[2][3]);
            o[3][0] = fmaf(a3, bv.x, o[3][0]); o[3][1] = fmaf(a3, bv.y, o[3][1]);
            o[3][2] = fmaf(a3, bv.z, o[3][2]); o[3][3] = fmaf(a3, bv.w, o[3][3]);
        }
    }

    // Reduce smod across tx lanes; normalize and write y [B,T,C]
#pragma unroll
    for (int i = 0; i < 4; i++) {
        float sm = smod[i];
        sm += __shfl_xor_sync(0xffffffffu, sm, 1);
        sm += __shfl_xor_sync(0xffffffffu, sm, 2);
        sm += __shfl_xor_sync(0xffffffffu, sm, 4);
        sm += __shfl_xor_sync(0xffffffffu, sm, 8);
        float dn = 1.f / (sm + 1e-8f);
        float4 out = make_float4(o[i][0] * dn, o[i][1] * dn,
                                 o[i][2] * dn, o[i][3] * dn);
        int t = qt * 64 + ty * 4 + i;
        *reinterpret_cast<float4*>(
            &g_y[((size_t)(b * SEQ + t)) * EMB + h * HDIM + tx * 4]) = out;
    }
}

// ---------------------------------------------------------------------------
extern "C" void kernel_launch(void* const* d_in, const int* in_sizes, int n_in,
                              void* d_out, int out_size)
{
    const float* x      = (const float*)d_in[0];
    const float* W_attn = (const float*)d_in[1];
    const float* b_attn = (const float*)d_in[2];
    const float* W_proj = (const float*)d_in[3];
    const float* b_proj = (const float*)d_in[4];
    const float* thr    = (const float*)d_in[5];
    const float* leak   = (const float*)d_in[6];
    const float* steep  = (const float*)d_in[7];
    float* out = (float*)d_out;

    gemm_qkv_kernel<<<dim3(NQKV / 128, MROWS / 128), 256>>>(x, W_attn, b_attn);
    lif_attn_kernel<<<dim3(SEQ / 64, NHEAD, BATCH), 256>>>(thr, leak, steep);
    gemm_proj_kernel<<<dim3(EMB / 128, MROWS / 128), 256>>>(W_proj, b_proj, out);
}

// round 14
// speedup vs baseline: 2.4645x; 1.0054x over previous
#include <cuda_runtime.h>
#include <math.h>

// Problem dims (fixed by the reference)
#define BATCH   2
#define SEQ     2048
#define EMB     1024
#define NHEAD   16
#define HDIM    64
#define MROWS   (BATCH * SEQ)   // 4096
#define NQKV    (3 * EMB)       // 3072

// Scratch (no cudaMalloc allowed): q/k/v in [B,H,T,hd], y in [B,T,C]
__device__ float g_q[BATCH * NHEAD * SEQ * HDIM];
__device__ float g_k[BATCH * NHEAD * SEQ * HDIM];
__device__ float g_v[BATCH * NHEAD * SEQ * HDIM];
__device__ float g_y[BATCH * SEQ * EMB];

// ---------------------------------------------------------------------------
// GEMM1: qkv = x @ W_attn + b_attn, scattered into g_q/g_k/g_v [B,H,T,hd]
// ---------------------------------------------------------------------------
__global__ void __launch_bounds__(256) gemm_qkv_kernel(
    const float* __restrict__ A,      // x [MROWS, EMB]
    const float* __restrict__ W,      // W_attn [EMB, NQKV]
    const float* __restrict__ bias)   // b_attn [NQKV]
{
    __shared__ float As[16][128];
    __shared__ float Bs[16][128];
    const int tid = threadIdx.x;
    const int tx = tid & 15;
    const int ty = tid >> 4;
    const int brow = blockIdx.y * 128;
    const int bcol = blockIdx.x * 128;

    float acc[8][8];
#pragma unroll
    for (int i = 0; i < 8; i++)
#pragma unroll
        for (int j = 0; j < 8; j++) acc[i][j] = 0.f;

    for (int k0 = 0; k0 < EMB; k0 += 16) {
#pragma unroll
        for (int i = 0; i < 2; i++) {
            int id = tid + i * 256;
            int r  = id >> 2;
            int c4 = (id & 3) * 4;
            float4 v = *reinterpret_cast<const float4*>(
                &A[(size_t)(brow + r) * EMB + k0 + c4]);
            As[c4 + 0][r] = v.x;
            As[c4 + 1][r] = v.y;
            As[c4 + 2][r] = v.z;
            As[c4 + 3][r] = v.w;
        }
#pragma unroll
        for (int i = 0; i < 2; i++) {
            int id = tid + i * 256;
            int r  = id >> 5;
            int c4 = (id & 31) * 4;
            *reinterpret_cast<float4*>(&Bs[r][c4]) =
                *reinterpret_cast<const float4*>(
                    &W[(size_t)(k0 + r) * NQKV + bcol + c4]);
        }
        __syncthreads();
#pragma unroll
        for (int kk = 0; kk < 16; kk++) {
            float a[8], b[8];
#pragma unroll
            for (int i = 0; i < 8; i++) a[i] = As[kk][ty * 8 + i];
#pragma unroll
            for (int j = 0; j < 8; j++) b[j] = Bs[kk][tx * 8 + j];
#pragma unroll
            for (int i = 0; i < 8; i++)
#pragma unroll
                for (int j = 0; j < 8; j++)
                    acc[i][j] = fmaf(a[i], b[j], acc[i][j]);
        }
        __syncthreads();
    }

    const int part = bcol / EMB;
    float* dst = (part == 0) ? g_q : ((part == 1) ? g_k : g_v);
#pragma unroll
    for (int i = 0; i < 8; i++) {
        int m  = brow + ty * 8 + i;
        int bb = m / SEQ;
        int t  = m % SEQ;
#pragma unroll
        for (int j = 0; j < 8; j++) {
            int n   = bcol + tx * 8 + j;
            int cin = n % EMB;
            int h   = cin / HDIM;
            int d   = cin % HDIM;
            dst[(((size_t)(bb * NHEAD + h)) * SEQ + t) * HDIM + d] =
                acc[i][j] + bias[n];
        }
    }
}

// ---------------------------------------------------------------------------
// GEMM2: out = y @ W_proj + b_proj   (y read from g_y [MROWS, EMB])
// ---------------------------------------------------------------------------
__global__ void __launch_bounds__(256) gemm_proj_kernel(
    const float* __restrict__ W,
    const float* __restrict__ bias,
    float* __restrict__ out)
{
    __shared__ float As[16][128];
    __shared__ float Bs[16][128];
    const int tid = threadIdx.x;
    const int tx = tid & 15;
    const int ty = tid >> 4;
    const int brow = blockIdx.y * 128;
    const int bcol = blockIdx.x * 128;

    float acc[8][8];
#pragma unroll
    for (int i = 0; i < 8; i++)
#pragma unroll
        for (int j = 0; j < 8; j++) acc[i][j] = 0.f;

    for (int k0 = 0; k0 < EMB; k0 += 16) {
#pragma unroll
        for (int i = 0; i < 2; i++) {
            int id = tid + i * 256;
            int r  = id >> 2;
            int c4 = (id & 3) * 4;
            float4 v = *reinterpret_cast<const float4*>(
                &g_y[(size_t)(brow + r) * EMB + k0 + c4]);
            As[c4 + 0][r] = v.x;
            As[c4 + 1][r] = v.y;
            As[c4 + 2][r] = v.z;
            As[c4 + 3][r] = v.w;
        }
#pragma unroll
        for (int i = 0; i < 2; i++) {
            int id = tid + i * 256;
            int r  = id >> 5;
            int c4 = (id & 31) * 4;
            *reinterpret_cast<float4*>(&Bs[r][c4]) =
                *reinterpret_cast<const float4*>(
                    &W[(size_t)(k0 + r) * EMB + bcol + c4]);
        }
        __syncthreads();
#pragma unroll
        for (int kk = 0; kk < 16; kk++) {
            float a[8], b[8];
#pragma unroll
            for (int i = 0; i < 8; i++) a[i] = As[kk][ty * 8 + i];
#pragma unroll
            for (int j = 0; j < 8; j++) b[j] = Bs[kk][tx * 8 + j];
#pragma unroll
            for (int i = 0; i < 8; i++)
#pragma unroll
                for (int j = 0; j < 8; j++)
                    acc[i][j] = fmaf(a[i], b[j], acc[i][j]);
        }
        __syncthreads();
    }

#pragma unroll
    for (int i = 0; i < 8; i++) {
        int m = brow + ty * 8 + i;
#pragma unroll
        for (int j = 0; j < 8; j++) {
            int n = bcol + tx * 8 + j;
            out[(size_t)m * EMB + n] = acc[i][j] + bias[n];
        }
    }
}

// ---------------------------------------------------------------------------
// Fused causal LIF attention, register-tiled GEMM formulation.
// Block = 64 queries of one (b,h). 256 threads as 16x16; each thread owns a
// 4x4 tile of the 64x64 score tile (QK pass) and a 4x4 tile of the 64x64
// output (PV pass). All loop bounds are BLOCK-UNIFORM (tile count qt+1);
// causality handled by predication on the diagonal tile only. Shuffles are
// executed by all lanes on every iteration -> no divergence hazard.
//
// SMEM (exactly 48KB):
//   Qs[d][r]  : Q^T, pre-scaled by 1/sqrt(hd), loaded once
//   KsU[.][.] : per tile, K^T [d][c] during QK; then mod [r][c] during PV
//   Vs[c][d]  : V tile, row-major
// ---------------------------------------------------------------------------
__global__ void __launch_bounds__(256) lif_attn_kernel(
    const float* __restrict__ thr_p,
    const float* __restrict__ leak_p,
    const float* __restrict__ steep_p)
{
    __shared__ float Qs [64][64];
    __shared__ float KsU[64][64];
    __shared__ float Vs [64][64];

    const int b   = blockIdx.z;
    const int h   = blockIdx.y;
    const int qt  = (gridDim.x - 1) - blockIdx.x;  // heavy blocks first
    const int tid = threadIdx.x;
    const int tx  = tid & 15;
    const int ty  = tid >> 4;

    // Per-head LIF params (robust softplus)
    const float sx  = steep_p[h];
    const float st  = fmaxf(sx, 0.f) + log1pf(__expf(-fabsf(sx)));
    const float lk  = 1.f / (1.f + __expf(-leak_p[h]));
    const float thr = fabsf(thr_p[h]) * 0.1f;

    const size_t bh = (size_t)(b * NHEAD + h) * SEQ * HDIM;
    const float* Kb = g_k + bh;
    const float* Vb = g_v + bh;
    const float* Qb = g_q + bh + (size_t)qt * 64 * HDIM;

    // Load Q transposed + scaled: Qs[d][r] = Q[r][d] / 8
#pragma unroll
    for (int i = 0; i < 4; i++) {
        int id = tid + i * 256;
        int r  = id & 63;
        int c4 = (id >> 6) * 4;
        float4 v = *reinterpret_cast<const float4*>(&Qb[r * HDIM + c4]);
        Qs[c4 + 0][r] = v.x * 0.125f;
        Qs[c4 + 1][r] = v.y * 0.125f;
        Qs[c4 + 2][r] = v.z * 0.125f;
        Qs[c4 + 3][r] = v.w * 0.125f;
    }

    float m[4], l[4];
#pragma unroll
    for (int i = 0; i < 4; i++) { m[i] = -1e30f; l[i] = 0.f; }

    const int nkt = qt + 1;

    // ================= Pass 1: softmax stats =================
    for (int kt = 0; kt < nkt; kt++) {
        __syncthreads();   // KsU readers done (and Q stores visible on kt=0)
#pragma unroll
        for (int i = 0; i < 4; i++) {
            int id = tid + i * 256;
            int r  = id & 63;
            int c4 = (id >> 6) * 4;
            float4 v = *reinterpret_cast<const float4*>(
                &Kb[(size_t)(kt * 64 + r) * HDIM + c4]);
            KsU[c4 + 0][r] = v.x;
            KsU[c4 + 1][r] = v.y;
            KsU[c4 + 2][r] = v.z;
            KsU[c4 + 3][r] = v.w;
        }
        __syncthreads();

        float s[4][4];
#pragma unroll
        for (int i = 0; i < 4; i++)
#pragma unroll
            for (int j = 0; j < 4; j++) s[i][j] = 0.f;

#pragma unroll 16
        for (int d = 0; d < 64; d++) {
            float4 a = *reinterpret_cast<const float4*>(&Qs[d][ty * 4]);
            float4 bb = *reinterpret_cast<const float4*>(&KsU[d][tx * 4]);
            float av[4] = {a.x, a.y, a.z, a.w};
            float bv[4] = {bb.x, bb.y, bb.z, bb.w};
#pragma unroll
            for (int i = 0; i < 4; i++)
#pragma unroll
                for (int j = 0; j < 4; j++)
                    s[i][j] = fmaf(av[i], bv[j], s[i][j]);
        }

        if (kt == qt) {  // diagonal tile: causal mask by predication
#pragma unroll
            for (int i = 0; i < 4; i++)
#pragma unroll
                for (int j = 0; j < 4; j++)
                    if (tx * 4 + j > ty * 4 + i) s[i][j] = -1e30f;
        }

        // Online (m, l) per row: reduce across the 16 tx lanes
#pragma unroll
        for (int i = 0; i < 4; i++) {
            float tm = fmaxf(fmaxf(s[i][0], s[i][1]), fmaxf(s[i][2], s[i][3]));
            tm = fmaxf(tm, __shfl_xor_sync(0xffffffffu, tm, 1));
            tm = fmaxf(tm, __shfl_xor_sync(0xffffffffu, tm, 2));
            tm = fmaxf(tm, __shfl_xor_sync(0xffffffffu, tm, 4));
            tm = fmaxf(tm, __shfl_xor_sync(0xffffffffu, tm, 8));
            float mn = fmaxf(m[i], tm);
            float e = __expf(s[i][0] - mn) + __expf(s[i][1] - mn)
                    + __expf(s[i][2] - mn) + __expf(s[i][3] - mn);
            e += __shfl_xor_sync(0xffffffffu, e, 1);
            e += __shfl_xor_sync(0xffffffffu, e, 2);
            e += __shfl_xor_sync(0xffffffffu, e, 4);
            e += __shfl_xor_sync(0xffffffffu, e, 8);
            l[i] = l[i] * __expf(m[i] - mn) + e;
            m[i] = mn;
        }
    }

    float linv[4];
#pragma unroll
    for (int i = 0; i < 4; i++) linv[i] = 1.f / l[i];  // l >= 1 always

    // ================= Pass 2: LIF modulation + PV =================
    float o[4][4];
#pragma unroll
    for (int i = 0; i < 4; i++)
#pragma unroll
        for (int j = 0; j < 4; j++) o[i][j] = 0.f;
    float smod[4] = {0.f, 0.f, 0.f, 0.f};

    for (int kt = 0; kt < nkt; kt++) {
        __syncthreads();   // previous PV readers of KsU/Vs done
#pragma unroll
        for (int i = 0; i < 4; i++) {
            int id = tid + i * 256;
            int r  = id & 63;
            int c4 = (id >> 6) * 4;
            float4 v = *reinterpret_cast<const float4*>(
                &Kb[(size_t)(kt * 64 + r) * HDIM + c4]);
            KsU[c4 + 0][r] = v.x;
            KsU[c4 + 1][r] = v.y;
            KsU[c4 + 2][r] = v.z;
            KsU[c4 + 3][r] = v.w;
        }
#pragma unroll
        for (int i = 0; i < 4; i++) {
            int id = tid + i * 256;
            int r  = id >> 4;
            int c4 = (id & 15) * 4;
            *reinterpret_cast<float4*>(&Vs[r][c4]) =
                *reinterpret_cast<const float4*>(
                    &Vb[(size_t)(kt * 64 + r) * HDIM + c4]);
        }
        __syncthreads();

        float s[4][4];
#pragma unroll
        for (int i = 0; i < 4; i++)
#pragma unroll
            for (int j = 0; j < 4; j++) s[i][j] = 0.f;

#pragma unroll 16
        for (int d = 0; d < 64; d++) {
            float4 a = *reinterpret_cast<const float4*>(&Qs[d][ty * 4]);
            float4 bb = *reinterpret_cast<const float4*>(&KsU[d][tx * 4]);
            float av[4] = {a.x, a.y, a.z, a.w};
            float bv[4] = {bb.x, bb.y, bb.z, bb.w};
#pragma unroll
            for (int i = 0; i < 4; i++)
#pragma unroll
                for (int j = 0; j < 4; j++)
                    s[i][j] = fmaf(av[i], bv[j], s[i][j]);
        }

        if (kt == qt) {
#pragma unroll
            for (int i = 0; i < 4; i++)
#pragma unroll
                for (int j = 0; j < 4; j++)
                    if (tx * 4 + j > ty * 4 + i) s[i][j] = -1e30f;
        }

        __syncthreads();   // everyone done reading KsU before overwrite as mod

        // mod = p * (lk + fire*(1-lk)); store [r][c] into KsU
#pragma unroll
        for (int i = 0; i < 4; i++) {
            float mo[4];
#pragma unroll
            for (int j = 0; j < 4; j++) {
                float p    = __expf(s[i][j] - m[i]) * linv[i];
                float fire = 1.f / (1.f + __expf(-st * (p - thr)));
                float w    = lk + fire * (1.f - lk);
                mo[j]      = p * w;
                smod[i]   += mo[j];
            }
            *reinterpret_cast<float4*>(&KsU[ty * 4 + i][tx * 4]) =
                make_float4(mo[0], mo[1], mo[2], mo[3]);
        }
        __syncthreads();

        // PV: o[r][d4] += sum_c mod[r][c] * V[c][d4]
#pragma unroll 8
        for (int c = 0; c < 64; c++) {
            float4 bv = *reinterpret_cast<const float4*>(&Vs[c][tx * 4]);
            float a0 = KsU[ty * 4 + 0][c];
            float a1 = KsU[ty * 4 + 1][c];
            float a2 = KsU[ty * 4 + 2][c];
            float a3 = KsU[ty * 4 + 3][c];
            o[0][0] = fmaf(a0, bv.x, o[0][0]); o[0][1] = fmaf(a0, bv.y, o[0][1]);
            o[0][2] = fmaf(a0, bv.z, o[0][2]); o[0][3] = fmaf(a0, bv.w, o[0][3]);
            o[1][0] = fmaf(a1, bv.x, o[1][0]); o[1][1] = fmaf(a1, bv.y, o[1][1]);
            o[1][2] = fmaf(a1, bv.z, o[1][2]); o[1][3] = fmaf(a1, bv.w, o[1][3]);
            o[2][0] = fmaf(a2, bv.x, o[2][0]); o[2][1] = fmaf(a2, bv.y, o[2][1]);
            o[2][2] = fmaf(a2, bv.z, o[2][2]); o[2][3] = fmaf(a2, bv.w, o[2][3]);
            o[3][0] = fmaf(a3, bv.x, o[3][0]); o[3][1] = fmaf(a3, bv.y, o[3][1]);
            o[3][2] = fmaf(a3, bv.z, o[3][2]); o[3][3] = fmaf(a3, bv.w, o[3][3]);
        }
    }

    // Reduce smod across tx lanes; normalize and write y [B,T,C]
#pragma unroll
    for (int i = 0; i < 4; i++) {
        float sm = smod[i];
        sm += __shfl_xor_sync(0xffffffffu, sm, 1);
        sm += __shfl_xor_sync(0xffffffffu, sm, 2);
        sm += __shfl_xor_sync(0xffffffffu, sm, 4);
        sm += __shfl_xor_sync(0xffffffffu, sm, 8);
        float dn = 1.f / (sm + 1e-8f);
        float4 out = make_float4(o[i][0] * dn, o[i][1] * dn,
                                 o[i][2] * dn, o[i][3] * dn);
        int t = qt * 64 + ty * 4 + i;
        *reinterpret_cast<float4*>(
            &g_y[((size_t)(b * SEQ + t)) * EMB + h * HDIM + tx * 4]) = out;
    }
}

// ---------------------------------------------------------------------------
extern "C" void kernel_launch(void* const* d_in, const int* in_sizes, int n_in,
                              void* d_out, int out_size)
{
    const float* x      = (const float*)d_in[0];
    const float* W_attn = (const float*)d_in[1];
    const float* b_attn = (const float*)d_in[2];
    const float* W_proj = (const float*)d_in[3];
    const float* b_proj = (const float*)d_in[4];
    const float* thr    = (const float*)d_in[5];
    const float* leak   = (const float*)d_in[6];
    const float* steep  = (const float*)d_in[7];
    float* out = (float*)d_out;

    gemm_qkv_kernel<<<dim3(NQKV / 128, MROWS / 128), 256>>>(x, W_attn, b_attn);
    lif_attn_kernel<<<dim3(SEQ / 64, NHEAD, BATCH), 256>>>(thr, leak, steep);
    gemm_proj_kernel<<<dim3(EMB / 128, MROWS / 128), 256>>>(W_proj, b_proj, out);
}

// round 15
// speedup vs baseline: 2.5492x; 1.0344x over previous
#include <cuda_runtime.h>
#include <math.h>

// Problem dims (fixed by the reference)
#define BATCH   2
#define SEQ     2048
#define EMB     1024
#define NHEAD   16
#define HDIM    64
#define MROWS   (BATCH * SEQ)   // 4096
#define NQKV    (3 * EMB)       // 3072

// Scratch (no cudaMalloc allowed): q/k/v in [B,H,T,hd], y in [B,T,C]
__device__ float g_q[BATCH * NHEAD * SEQ * HDIM];
__device__ float g_k[BATCH * NHEAD * SEQ * HDIM];
__device__ float g_v[BATCH * NHEAD * SEQ * HDIM];
__device__ float g_y[BATCH * SEQ * EMB];

// ---------------------------------------------------------------------------
// GEMM1: qkv = x @ W_attn + b_attn, scattered into g_q/g_k/g_v [B,H,T,hd]
// 128x128 block tile, BK=32 (R6 structure, wider slab), 256 threads, 8x8/thr.
// As padded to stride 132 to break transposed-store bank conflicts.
// ---------------------------------------------------------------------------
__global__ void __launch_bounds__(256) gemm_qkv_kernel(
    const float* __restrict__ A,      // x [MROWS, EMB]
    const float* __restrict__ W,      // W_attn [EMB, NQKV]
    const float* __restrict__ bias)   // b_attn [NQKV]
{
    __shared__ float As[32][132];
    __shared__ float Bs[32][128];
    const int tid = threadIdx.x;
    const int tx = tid & 15;
    const int ty = tid >> 4;
    const int brow = blockIdx.y * 128;
    const int bcol = blockIdx.x * 128;

    float acc[8][8];
#pragma unroll
    for (int i = 0; i < 8; i++)
#pragma unroll
        for (int j = 0; j < 8; j++) acc[i][j] = 0.f;

    for (int k0 = 0; k0 < EMB; k0 += 32) {
#pragma unroll
        for (int i = 0; i < 4; i++) {
            int id = tid + i * 256;
            int r  = id >> 3;            // 0..127
            int c4 = (id & 7) * 4;       // 0,4,...,28
            float4 v = *reinterpret_cast<const float4*>(
                &A[(size_t)(brow + r) * EMB + k0 + c4]);
            As[c4 + 0][r] = v.x;
            As[c4 + 1][r] = v.y;
            As[c4 + 2][r] = v.z;
            As[c4 + 3][r] = v.w;
        }
#pragma unroll
        for (int i = 0; i < 4; i++) {
            int id = tid + i * 256;
            int r  = id >> 5;            // 0..31
            int c4 = (id & 31) * 4;      // 0..124
            *reinterpret_cast<float4*>(&Bs[r][c4]) =
                *reinterpret_cast<const float4*>(
                    &W[(size_t)(k0 + r) * NQKV + bcol + c4]);
        }
        __syncthreads();
#pragma unroll
        for (int kk = 0; kk < 32; kk++) {
            float a[8], b[8];
#pragma unroll
            for (int i = 0; i < 8; i++) a[i] = As[kk][ty * 8 + i];
#pragma unroll
            for (int j = 0; j < 8; j++) b[j] = Bs[kk][tx * 8 + j];
#pragma unroll
            for (int i = 0; i < 8; i++)
#pragma unroll
                for (int j = 0; j < 8; j++)
                    acc[i][j] = fmaf(a[i], b[j], acc[i][j]);
        }
        __syncthreads();
    }

    const int part = bcol / EMB;
    float* dst = (part == 0) ? g_q : ((part == 1) ? g_k : g_v);
#pragma unroll
    for (int i = 0; i < 8; i++) {
        int m  = brow + ty * 8 + i;
        int bb = m / SEQ;
        int t  = m % SEQ;
#pragma unroll
        for (int j = 0; j < 8; j++) {
            int n   = bcol + tx * 8 + j;
            int cin = n % EMB;
            int h   = cin / HDIM;
            int d   = cin % HDIM;
            dst[(((size_t)(bb * NHEAD + h)) * SEQ + t) * HDIM + d] =
                acc[i][j] + bias[n];
        }
    }
}

// ---------------------------------------------------------------------------
// GEMM2: out = y @ W_proj + b_proj   (y read from g_y [MROWS, EMB]), BK=32
// ---------------------------------------------------------------------------
__global__ void __launch_bounds__(256) gemm_proj_kernel(
    const float* __restrict__ W,
    const float* __restrict__ bias,
    float* __restrict__ out)
{
    __shared__ float As[32][132];
    __shared__ float Bs[32][128];
    const int tid = threadIdx.x;
    const int tx = tid & 15;
    const int ty = tid >> 4;
    const int brow = blockIdx.y * 128;
    const int bcol = blockIdx.x * 128;

    float acc[8][8];
#pragma unroll
    for (int i = 0; i < 8; i++)
#pragma unroll
        for (int j = 0; j < 8; j++) acc[i][j] = 0.f;

    for (int k0 = 0; k0 < EMB; k0 += 32) {
#pragma unroll
        for (int i = 0; i < 4; i++) {
            int id = tid + i * 256;
            int r  = id >> 3;
            int c4 = (id & 7) * 4;
            float4 v = *reinterpret_cast<const float4*>(
                &g_y[(size_t)(brow + r) * EMB + k0 + c4]);
            As[c4 + 0][r] = v.x;
            As[c4 + 1][r] = v.y;
            As[c4 + 2][r] = v.z;
            As[c4 + 3][r] = v.w;
        }
#pragma unroll
        for (int i = 0; i < 4; i++) {
            int id = tid + i * 256;
            int r  = id >> 5;
            int c4 = (id & 31) * 4;
            *reinterpret_cast<float4*>(&Bs[r][c4]) =
                *reinterpret_cast<const float4*>(
                    &W[(size_t)(k0 + r) * EMB + bcol + c4]);
        }
        __syncthreads();
#pragma unroll
        for (int kk = 0; kk < 32; kk++) {
            float a[8], b[8];
#pragma unroll
            for (int i = 0; i < 8; i++) a[i] = As[kk][ty * 8 + i];
#pragma unroll
            for (int j = 0; j < 8; j++) b[j] = Bs[kk][tx * 8 + j];
#pragma unroll
            for (int i = 0; i < 8; i++)
#pragma unroll
                for (int j = 0; j < 8; j++)
                    acc[i][j] = fmaf(a[i], b[j], acc[i][j]);
        }
        __syncthreads();
    }

#pragma unroll
    for (int i = 0; i < 8; i++) {
        int m = brow + ty * 8 + i;
#pragma unroll
        for (int j = 0; j < 8; j++) {
            int n = bcol + tx * 8 + j;
            out[(size_t)m * EMB + n] = acc[i][j] + bias[n];
        }
    }
}

// ---------------------------------------------------------------------------
// Fused causal LIF attention (byte-identical to the verified R6/R14 kernel)
// ---------------------------------------------------------------------------
__global__ void __launch_bounds__(256) lif_attn_kernel(
    const float* __restrict__ thr_p,
    const float* __restrict__ leak_p,
    const float* __restrict__ steep_p)
{
    __shared__ float Qs [64][64];
    __shared__ float KsU[64][64];
    __shared__ float Vs [64][64];

    const int b   = blockIdx.z;
    const int h   = blockIdx.y;
    const int qt  = (gridDim.x - 1) - blockIdx.x;  // heavy blocks first
    const int tid = threadIdx.x;
    const int tx  = tid & 15;
    const int ty  = tid >> 4;

    const float sx  = steep_p[h];
    const float st  = fmaxf(sx, 0.f) + log1pf(__expf(-fabsf(sx)));
    const float lk  = 1.f / (1.f + __expf(-leak_p[h]));
    const float thr = fabsf(thr_p[h]) * 0.1f;

    const size_t bh = (size_t)(b * NHEAD + h) * SEQ * HDIM;
    const float* Kb = g_k + bh;
    const float* Vb = g_v + bh;
    const float* Qb = g_q + bh + (size_t)qt * 64 * HDIM;

#pragma unroll
    for (int i = 0; i < 4; i++) {
        int id = tid + i * 256;
        int r  = id & 63;
        int c4 = (id >> 6) * 4;
        float4 v = *reinterpret_cast<const float4*>(&Qb[r * HDIM + c4]);
        Qs[c4 + 0][r] = v.x * 0.125f;
        Qs[c4 + 1][r] = v.y * 0.125f;
        Qs[c4 + 2][r] = v.z * 0.125f;
        Qs[c4 + 3][r] = v.w * 0.125f;
    }

    float m[4], l[4];
#pragma unroll
    for (int i = 0; i < 4; i++) { m[i] = -1e30f; l[i] = 0.f; }

    const int nkt = qt + 1;

    // ================= Pass 1: softmax stats =================
    for (int kt = 0; kt < nkt; kt++) {
        __syncthreads();
#pragma unroll
        for (int i = 0; i < 4; i++) {
            int id = tid + i * 256;
            int r  = id & 63;
            int c4 = (id >> 6) * 4;
            float4 v = *reinterpret_cast<const float4*>(
                &Kb[(size_t)(kt * 64 + r) * HDIM + c4]);
            KsU[c4 + 0][r] = v.x;
            KsU[c4 + 1][r] = v.y;
            KsU[c4 + 2][r] = v.z;
            KsU[c4 + 3][r] = v.w;
        }
        __syncthreads();

        float s[4][4];
#pragma unroll
        for (int i = 0; i < 4; i++)
#pragma unroll
            for (int j = 0; j < 4; j++) s[i][j] = 0.f;

#pragma unroll 16
        for (int d = 0; d < 64; d++) {
            float4 a = *reinterpret_cast<const float4*>(&Qs[d][ty * 4]);
            float4 bb = *reinterpret_cast<const float4*>(&KsU[d][tx * 4]);
            float av[4] = {a.x, a.y, a.z, a.w};
            float bv[4] = {bb.x, bb.y, bb.z, bb.w};
#pragma unroll
            for (int i = 0; i < 4; i++)
#pragma unroll
                for (int j = 0; j < 4; j++)
                    s[i][j] = fmaf(av[i], bv[j], s[i][j]);
        }

        if (kt == qt) {
#pragma unroll
            for (int i = 0; i < 4; i++)
#pragma unroll
                for (int j = 0; j < 4; j++)
                    if (tx * 4 + j > ty * 4 + i) s[i][j] = -1e30f;
        }

#pragma unroll
        for (int i = 0; i < 4; i++) {
            float tm = fmaxf(fmaxf(s[i][0], s[i][1]), fmaxf(s[i][2], s[i][3]));
            tm = fmaxf(tm, __shfl_xor_sync(0xffffffffu, tm, 1));
            tm = fmaxf(tm, __shfl_xor_sync(0xffffffffu, tm, 2));
            tm = fmaxf(tm, __shfl_xor_sync(0xffffffffu, tm, 4));
            tm = fmaxf(tm, __shfl_xor_sync(0xffffffffu, tm, 8));
            float mn = fmaxf(m[i], tm);
            float e = __expf(s[i][0] - mn) + __expf(s[i][1] - mn)
                    + __expf(s[i][2] - mn) + __expf(s[i][3] - mn);
            e += __shfl_xor_sync(0xffffffffu, e, 1);
            e += __shfl_xor_sync(0xffffffffu, e, 2);
            e += __shfl_xor_sync(0xffffffffu, e, 4);
            e += __shfl_xor_sync(0xffffffffu, e, 8);
            l[i] = l[i] * __expf(m[i] - mn) + e;
            m[i] = mn;
        }
    }

    float linv[4];
#pragma unroll
    for (int i = 0; i < 4; i++) linv[i] = 1.f / l[i];

    // ================= Pass 2: LIF modulation + PV =================
    float o[4][4];
#pragma unroll
    for (int i = 0; i < 4; i++)
#pragma unroll
        for (int j = 0; j < 4; j++) o[i][j] = 0.f;
    float smod[4] = {0.f, 0.f, 0.f, 0.f};

    for (int kt = 0; kt < nkt; kt++) {
        __syncthreads();
#pragma unroll
        for (int i = 0; i < 4; i++) {
            int id = tid + i * 256;
            int r  = id & 63;
            int c4 = (id >> 6) * 4;
            float4 v = *reinterpret_cast<const float4*>(
                &Kb[(size_t)(kt * 64 + r) * HDIM + c4]);
            KsU[c4 + 0][r] = v.x;
            KsU[c4 + 1][r] = v.y;
            KsU[c4 + 2][r] = v.z;
            KsU[c4 + 3][r] = v.w;
        }
#pragma unroll
        for (int i = 0; i < 4; i++) {
            int id = tid + i * 256;
            int r  = id >> 4;
            int c4 = (id & 15) * 4;
            *reinterpret_cast<float4*>(&Vs[r][c4]) =
                *reinterpret_cast<const float4*>(
                    &Vb[(size_t)(kt * 64 + r) * HDIM + c4]);
        }
        __syncthreads();

        float s[4][4];
#pragma unroll
        for (int i = 0; i < 4; i++)
#pragma unroll
            for (int j = 0; j < 4; j++) s[i][j] = 0.f;

#pragma unroll 16
        for (int d = 0; d < 64; d++) {
            float4 a = *reinterpret_cast<const float4*>(&Qs[d][ty * 4]);
            float4 bb = *reinterpret_cast<const float4*>(&KsU[d][tx * 4]);
            float av[4] = {a.x, a.y, a.z, a.w};
            float bv[4] = {bb.x, bb.y, bb.z, bb.w};
#pragma unroll
            for (int i = 0; i < 4; i++)
#pragma unroll
                for (int j = 0; j < 4; j++)
                    s[i][j] = fmaf(av[i], bv[j], s[i][j]);
        }

        if (kt == qt) {
#pragma unroll
            for (int i = 0; i < 4; i++)
#pragma unroll
                for (int j = 0; j < 4; j++)
                    if (tx * 4 + j > ty * 4 + i) s[i][j] = -1e30f;
        }

        __syncthreads();

#pragma unroll
        for (int i = 0; i < 4; i++) {
            float mo[4];
#pragma unroll
            for (int j = 0; j < 4; j++) {
                float p    = __expf(s[i][j] - m[i]) * linv[i];
                float fire = 1.f / (1.f + __expf(-st * (p - thr)));
                float w    = lk + fire * (1.f - lk);
                mo[j]      = p * w;
                smod[i]   += mo[j];
            }
            *reinterpret_cast<float4*>(&KsU[ty * 4 + i][tx * 4]) =
                make_float4(mo[0], mo[1], mo[2], mo[3]);
        }
        __syncthreads();

#pragma unroll 8
        for (int c = 0; c < 64; c++) {
            float4 bv = *reinterpret_cast<const float4*>(&Vs[c][tx * 4]);
            float a0 = KsU[ty * 4 + 0][c];
            float a1 = KsU[ty * 4 + 1][c];
            float a2 = KsU[ty * 4 + 2][c];
            float a3 = KsU[ty * 4 + 3][c];
            o[0][0] = fmaf(a0, bv.x, o[0][0]); o[0][1] = fmaf(a0, bv.y, o[0][1]);
            o[0][2] = fmaf(a0, bv.z, o[0][2]); o[0][3] = fmaf(a0, bv.w, o[0][3]);
            o[1][0] = fmaf(a1, bv.x, o[1][0]); o[1][1] = fmaf(a1, bv.y, o[1][1]);
            o[1][2] = fmaf(a1, bv.z, o[1][2]); o[1][3] = fmaf(a1, bv.w, o[1][3]);
            o[2][0] = fmaf(a2, bv.x, o[2][0]); o[2][1] = fmaf(a2, bv.y, o[2][1]);
            o[2][2] = fmaf(a2, bv.z, o[2][2]); o[2][3] = fmaf(a2, bv.w, o[2][3]);
            o[3][0] = fmaf(a3, bv.x, o[3][0]); o[3][1] = fmaf(a3, bv.y, o[3][1]);
            o[3][2] = fmaf(a3, bv.z, o[3][2]); o[3][3] = fmaf(a3, bv.w, o[3][3]);
        }
    }

#pragma unroll
    for (int i = 0; i < 4; i++) {
        float sm = smod[i];
        sm += __shfl_xor_sync(0xffffffffu, sm, 1);
        sm += __shfl_xor_sync(0xffffffffu, sm, 2);
        sm += __shfl_xor_sync(0xffffffffu, sm, 4);
        sm += __shfl_xor_sync(0xffffffffu, sm, 8);
        float dn = 1.f / (sm + 1e-8f);
        float4 out = make_float4(o[i][0] * dn, o[i][1] * dn,
                                 o[i][2] * dn, o[i][3] * dn);
        int t = qt * 64 + ty * 4 + i;
        *reinterpret_cast<float4*>(
            &g_y[((size_t)(b * SEQ + t)) * EMB + h * HDIM + tx * 4]) = out;
    }
}

// ---------------------------------------------------------------------------
extern "C" void kernel_launch(void* const* d_in, const int* in_sizes, int n_in,
                              void* d_out, int out_size)
{
    const float* x      = (const float*)d_in[0];
    const float* W_attn = (const float*)d_in[1];
    const float* b_attn = (const float*)d_in[2];
    const float* W_proj = (const float*)d_in[3];
    const float* b_proj = (const float*)d_in[4];
    const float* thr    = (const float*)d_in[5];
    const float* leak   = (const float*)d_in[6];
    const float* steep  = (const float*)d_in[7];
    float* out = (float*)d_out;

    gemm_qkv_kernel<<<dim3(NQKV / 128, MROWS / 128), 256>>>(x, W_attn, b_attn);
    lif_attn_kernel<<<dim3(SEQ / 64, NHEAD, BATCH), 256>>>(thr, leak, steep);
    gemm_proj_kernel<<<dim3(EMB / 128, MROWS / 128), 256>>>(W_proj, b_proj, out);
}

// round 16
// speedup vs baseline: 2.6178x; 1.0269x over previous
#include <cuda_runtime.h>
#include <math.h>

// Problem dims (fixed by the reference)
#define BATCH   2
#define SEQ     2048
#define EMB     1024
#define NHEAD   16
#define HDIM    64
#define MROWS   (BATCH * SEQ)   // 4096
#define NQKV    (3 * EMB)       // 3072

// Scratch (no cudaMalloc allowed): q/k/v in [B,H,T,hd], y in [B,T,C]
__device__ float g_q[BATCH * NHEAD * SEQ * HDIM];
__device__ float g_k[BATCH * NHEAD * SEQ * HDIM];
__device__ float g_v[BATCH * NHEAD * SEQ * HDIM];
__device__ float g_y[BATCH * SEQ * EMB];

// ---------------------------------------------------------------------------
// GEMM1: qkv = x @ W_attn + b_attn, scattered into g_q/g_k/g_v [B,H,T,hd]
// Block tile 128M x 64N, BK=32, 256 threads (16x16), 8x4 per thread.
// Small register footprint (~32 acc) -> 2 CTAs/SM for cross-CTA latency hiding.
// ---------------------------------------------------------------------------
__global__ void __launch_bounds__(256) gemm_qkv_kernel(
    const float* __restrict__ A,      // x [MROWS, EMB]
    const float* __restrict__ W,      // W_attn [EMB, NQKV]
    const float* __restrict__ bias)   // b_attn [NQKV]
{
    __shared__ float As[32][132];
    __shared__ float Bs[32][64];
    const int tid = threadIdx.x;
    const int tx = tid & 15;
    const int ty = tid >> 4;
    const int brow = blockIdx.y * 128;
    const int bcol = blockIdx.x * 64;

    float acc[8][4];
#pragma unroll
    for (int i = 0; i < 8; i++)
#pragma unroll
        for (int j = 0; j < 4; j++) acc[i][j] = 0.f;

    for (int k0 = 0; k0 < EMB; k0 += 32) {
#pragma unroll
        for (int i = 0; i < 4; i++) {
            int id = tid + i * 256;
            int r  = id >> 3;            // 0..127
            int c4 = (id & 7) * 4;       // 0,4,...,28
            float4 v = *reinterpret_cast<const float4*>(
                &A[(size_t)(brow + r) * EMB + k0 + c4]);
            As[c4 + 0][r] = v.x;
            As[c4 + 1][r] = v.y;
            As[c4 + 2][r] = v.z;
            As[c4 + 3][r] = v.w;
        }
#pragma unroll
        for (int i = 0; i < 2; i++) {
            int id = tid + i * 256;
            int r  = id >> 4;            // 0..31
            int c4 = (id & 15) * 4;      // 0..60
            *reinterpret_cast<float4*>(&Bs[r][c4]) =
                *reinterpret_cast<const float4*>(
                    &W[(size_t)(k0 + r) * NQKV + bcol + c4]);
        }
        __syncthreads();
#pragma unroll
        for (int kk = 0; kk < 32; kk++) {
            float a[8], b[4];
#pragma unroll
            for (int i = 0; i < 8; i++) a[i] = As[kk][ty * 8 + i];
#pragma unroll
            for (int j = 0; j < 4; j++) b[j] = Bs[kk][tx * 4 + j];
#pragma unroll
            for (int i = 0; i < 8; i++)
#pragma unroll
                for (int j = 0; j < 4; j++)
                    acc[i][j] = fmaf(a[i], b[j], acc[i][j]);
        }
        __syncthreads();
    }

    // 64-wide N tile never crosses a q/k/v boundary nor a head boundary.
    const int part = bcol / EMB;
    float* dst = (part == 0) ? g_q : ((part == 1) ? g_k : g_v);
#pragma unroll
    for (int i = 0; i < 8; i++) {
        int m  = brow + ty * 8 + i;
        int bb = m / SEQ;
        int t  = m % SEQ;
#pragma unroll
        for (int j = 0; j < 4; j++) {
            int n   = bcol + tx * 4 + j;
            int cin = n % EMB;
            int h   = cin / HDIM;
            int d   = cin % HDIM;
            dst[(((size_t)(bb * NHEAD + h)) * SEQ + t) * HDIM + d] =
                acc[i][j] + bias[n];
        }
    }
}

// ---------------------------------------------------------------------------
// GEMM2: out = y @ W_proj + b_proj   (y read from g_y), same 128x64 tiling
// ---------------------------------------------------------------------------
__global__ void __launch_bounds__(256) gemm_proj_kernel(
    const float* __restrict__ W,
    const float* __restrict__ bias,
    float* __restrict__ out)
{
    __shared__ float As[32][132];
    __shared__ float Bs[32][64];
    const int tid = threadIdx.x;
    const int tx = tid & 15;
    const int ty = tid >> 4;
    const int brow = blockIdx.y * 128;
    const int bcol = blockIdx.x * 64;

    float acc[8][4];
#pragma unroll
    for (int i = 0; i < 8; i++)
#pragma unroll
        for (int j = 0; j < 4; j++) acc[i][j] = 0.f;

    for (int k0 = 0; k0 < EMB; k0 += 32) {
#pragma unroll
        for (int i = 0; i < 4; i++) {
            int id = tid + i * 256;
            int r  = id >> 3;
            int c4 = (id & 7) * 4;
            float4 v = *reinterpret_cast<const float4*>(
                &g_y[(size_t)(brow + r) * EMB + k0 + c4]);
            As[c4 + 0][r] = v.x;
            As[c4 + 1][r] = v.y;
            As[c4 + 2][r] = v.z;
            As[c4 + 3][r] = v.w;
        }
#pragma unroll
        for (int i = 0; i < 2; i++) {
            int id = tid + i * 256;
            int r  = id >> 4;
            int c4 = (id & 15) * 4;
            *reinterpret_cast<float4*>(&Bs[r][c4]) =
                *reinterpret_cast<const float4*>(
                    &W[(size_t)(k0 + r) * EMB + bcol + c4]);
        }
        __syncthreads();
#pragma unroll
        for (int kk = 0; kk < 32; kk++) {
            float a[8], b[4];
#pragma unroll
            for (int i = 0; i < 8; i++) a[i] = As[kk][ty * 8 + i];
#pragma unroll
            for (int j = 0; j < 4; j++) b[j] = Bs[kk][tx * 4 + j];
#pragma unroll
            for (int i = 0; i < 8; i++)
#pragma unroll
                for (int j = 0; j < 4; j++)
                    acc[i][j] = fmaf(a[i], b[j], acc[i][j]);
        }
        __syncthreads();
    }

#pragma unroll
    for (int i = 0; i < 8; i++) {
        int m = brow + ty * 8 + i;
#pragma unroll
        for (int j = 0; j < 4; j++) {
            int n = bcol + tx * 4 + j;
            out[(size_t)m * EMB + n] = acc[i][j] + bias[n];
        }
    }
}

// ---------------------------------------------------------------------------
// Fused causal LIF attention (byte-identical to the verified R6/R14 kernel)
// ---------------------------------------------------------------------------
__global__ void __launch_bounds__(256) lif_attn_kernel(
    const float* __restrict__ thr_p,
    const float* __restrict__ leak_p,
    const float* __restrict__ steep_p)
{
    __shared__ float Qs [64][64];
    __shared__ float KsU[64][64];
    __shared__ float Vs [64][64];

    const int b   = blockIdx.z;
    const int h   = blockIdx.y;
    const int qt  = (gridDim.x - 1) - blockIdx.x;  // heavy blocks first
    const int tid = threadIdx.x;
    const int tx  = tid & 15;
    const int ty  = tid >> 4;

    const float sx  = steep_p[h];
    const float st  = fmaxf(sx, 0.f) + log1pf(__expf(-fabsf(sx)));
    const float lk  = 1.f / (1.f + __expf(-leak_p[h]));
    const float thr = fabsf(thr_p[h]) * 0.1f;

    const size_t bh = (size_t)(b * NHEAD + h) * SEQ * HDIM;
    const float* Kb = g_k + bh;
    const float* Vb = g_v + bh;
    const float* Qb = g_q + bh + (size_t)qt * 64 * HDIM;

#pragma unroll
    for (int i = 0; i < 4; i++) {
        int id = tid + i * 256;
        int r  = id & 63;
        int c4 = (id >> 6) * 4;
        float4 v = *reinterpret_cast<const float4*>(&Qb[r * HDIM + c4]);
        Qs[c4 + 0][r] = v.x * 0.125f;
        Qs[c4 + 1][r] = v.y * 0.125f;
        Qs[c4 + 2][r] = v.z * 0.125f;
        Qs[c4 + 3][r] = v.w * 0.125f;
    }

    float m[4], l[4];
#pragma unroll
    for (int i = 0; i < 4; i++) { m[i] = -1e30f; l[i] = 0.f; }

    const int nkt = qt + 1;

    // ================= Pass 1: softmax stats =================
    for (int kt = 0; kt < nkt; kt++) {
        __syncthreads();
#pragma unroll
        for (int i = 0; i < 4; i++) {
            int id = tid + i * 256;
            int r  = id & 63;
            int c4 = (id >> 6) * 4;
            float4 v = *reinterpret_cast<const float4*>(
                &Kb[(size_t)(kt * 64 + r) * HDIM + c4]);
            KsU[c4 + 0][r] = v.x;
            KsU[c4 + 1][r] = v.y;
            KsU[c4 + 2][r] = v.z;
            KsU[c4 + 3][r] = v.w;
        }
        __syncthreads();

        float s[4][4];
#pragma unroll
        for (int i = 0; i < 4; i++)
#pragma unroll
            for (int j = 0; j < 4; j++) s[i][j] = 0.f;

#pragma unroll 16
        for (int d = 0; d < 64; d++) {
            float4 a = *reinterpret_cast<const float4*>(&Qs[d][ty * 4]);
            float4 bb = *reinterpret_cast<const float4*>(&KsU[d][tx * 4]);
            float av[4] = {a.x, a.y, a.z, a.w};
            float bv[4] = {bb.x, bb.y, bb.z, bb.w};
#pragma unroll
            for (int i = 0; i < 4; i++)
#pragma unroll
                for (int j = 0; j < 4; j++)
                    s[i][j] = fmaf(av[i], bv[j], s[i][j]);
        }

        if (kt == qt) {
#pragma unroll
            for (int i = 0; i < 4; i++)
#pragma unroll
                for (int j = 0; j < 4; j++)
                    if (tx * 4 + j > ty * 4 + i) s[i][j] = -1e30f;
        }

#pragma unroll
        for (int i = 0; i < 4; i++) {
            float tm = fmaxf(fmaxf(s[i][0], s[i][1]), fmaxf(s[i][2], s[i][3]));
            tm = fmaxf(tm, __shfl_xor_sync(0xffffffffu, tm, 1));
            tm = fmaxf(tm, __shfl_xor_sync(0xffffffffu, tm, 2));
            tm = fmaxf(tm, __shfl_xor_sync(0xffffffffu, tm, 4));
            tm = fmaxf(tm, __shfl_xor_sync(0xffffffffu, tm, 8));
            float mn = fmaxf(m[i], tm);
            float e = __expf(s[i][0] - mn) + __expf(s[i][1] - mn)
                    + __expf(s[i][2] - mn) + __expf(s[i][3] - mn);
            e += __shfl_xor_sync(0xffffffffu, e, 1);
            e += __shfl_xor_sync(0xffffffffu, e, 2);
            e += __shfl_xor_sync(0xffffffffu, e, 4);
            e += __shfl_xor_sync(0xffffffffu, e, 8);
            l[i] = l[i] * __expf(m[i] - mn) + e;
            m[i] = mn;
        }
    }

    float linv[4];
#pragma unroll
    for (int i = 0; i < 4; i++) linv[i] = 1.f / l[i];

    // ================= Pass 2: LIF modulation + PV =================
    float o[4][4];
#pragma unroll
    for (int i = 0; i < 4; i++)
#pragma unroll
        for (int j = 0; j < 4; j++) o[i][j] = 0.f;
    float smod[4] = {0.f, 0.f, 0.f, 0.f};

    for (int kt = 0; kt < nkt; kt++) {
        __syncthreads();
#pragma unroll
        for (int i = 0; i < 4; i++) {
            int id = tid + i * 256;
            int r  = id & 63;
            int c4 = (id >> 6) * 4;
            float4 v = *reinterpret_cast<const float4*>(
                &Kb[(size_t)(kt * 64 + r) * HDIM + c4]);
            KsU[c4 + 0][r] = v.x;
            KsU[c4 + 1][r] = v.y;
            KsU[c4 + 2][r] = v.z;
            KsU[c4 + 3][r] = v.w;
        }
#pragma unroll
        for (int i = 0; i < 4; i++) {
            int id = tid + i * 256;
            int r  = id >> 4;
            int c4 = (id & 15) * 4;
            *reinterpret_cast<float4*>(&Vs[r][c4]) =
                *reinterpret_cast<const float4*>(
                    &Vb[(size_t)(kt * 64 + r) * HDIM + c4]);
        }
        __syncthreads();

        float s[4][4];
#pragma unroll
        for (int i = 0; i < 4; i++)
#pragma unroll
            for (int j = 0; j < 4; j++) s[i][j] = 0.f;

#pragma unroll 16
        for (int d = 0; d < 64; d++) {
            float4 a = *reinterpret_cast<const float4*>(&Qs[d][ty * 4]);
            float4 bb = *reinterpret_cast<const float4*>(&KsU[d][tx * 4]);
            float av[4] = {a.x, a.y, a.z, a.w};
            float bv[4] = {bb.x, bb.y, bb.z, bb.w};
#pragma unroll
            for (int i = 0; i < 4; i++)
#pragma unroll
                for (int j = 0; j < 4; j++)
                    s[i][j] = fmaf(av[i], bv[j], s[i][j]);
        }

        if (kt == qt) {
#pragma unroll
            for (int i = 0; i < 4; i++)
#pragma unroll
                for (int j = 0; j < 4; j++)
                    if (tx * 4 + j > ty * 4 + i) s[i][j] = -1e30f;
        }

        __syncthreads();

#pragma unroll
        for (int i = 0; i < 4; i++) {
            float mo[4];
#pragma unroll
            for (int j = 0; j < 4; j++) {
                float p    = __expf(s[i][j] - m[i]) * linv[i];
                float fire = 1.f / (1.f + __expf(-st * (p - thr)));
                float w    = lk + fire * (1.f - lk);
                mo[j]      = p * w;
                smod[i]   += mo[j];
            }
            *reinterpret_cast<float4*>(&KsU[ty * 4 + i][tx * 4]) =
                make_float4(mo[0], mo[1], mo[2], mo[3]);
        }
        __syncthreads();

#pragma unroll 8
        for (int c = 0; c < 64; c++) {
            float4 bv = *reinterpret_cast<const float4*>(&Vs[c][tx * 4]);
            float a0 = KsU[ty * 4 + 0][c];
            float a1 = KsU[ty * 4 + 1][c];
            float a2 = KsU[ty * 4 + 2][c];
            float a3 = KsU[ty * 4 + 3][c];
            o[0][0] = fmaf(a0, bv.x, o[0][0]); o[0][1] = fmaf(a0, bv.y, o[0][1]);
            o[0][2] = fmaf(a0, bv.z, o[0][2]); o[0][3] = fmaf(a0, bv.w, o[0][3]);
            o[1][0] = fmaf(a1, bv.x, o[1][0]); o[1][1] = fmaf(a1, bv.y, o[1][1]);
            o[1][2] = fmaf(a1, bv.z, o[1][2]); o[1][3] = fmaf(a1, bv.w, o[1][3]);
            o[2][0] = fmaf(a2, bv.x, o[2][0]); o[2][1] = fmaf(a2, bv.y, o[2][1]);
            o[2][2] = fmaf(a2, bv.z, o[2][2]); o[2][3] = fmaf(a2, bv.w, o[2][3]);
            o[3][0] = fmaf(a3, bv.x, o[3][0]); o[3][1] = fmaf(a3, bv.y, o[3][1]);
            o[3][2] = fmaf(a3, bv.z, o[3][2]); o[3][3] = fmaf(a3, bv.w, o[3][3]);
        }
    }

#pragma unroll
    for (int i = 0; i < 4; i++) {
        float sm = smod[i];
        sm += __shfl_xor_sync(0xffffffffu, sm, 1);
        sm += __shfl_xor_sync(0xffffffffu, sm, 2);
        sm += __shfl_xor_sync(0xffffffffu, sm, 4);
        sm += __shfl_xor_sync(0xffffffffu, sm, 8);
        float dn = 1.f / (sm + 1e-8f);
        float4 out = make_float4(o[i][0] * dn, o[i][1] * dn,
                                 o[i][2] * dn, o[i][3] * dn);
        int t = qt * 64 + ty * 4 + i;
        *reinterpret_cast<float4*>(
            &g_y[((size_t)(b * SEQ + t)) * EMB + h * HDIM + tx * 4]) = out;
    }
}

// ---------------------------------------------------------------------------
extern "C" void kernel_launch(void* const* d_in, const int* in_sizes, int n_in,
                              void* d_out, int out_size)
{
    const float* x      = (const float*)d_in[0];
    const float* W_attn = (const float*)d_in[1];
    const float* b_attn = (const float*)d_in[2];
    const float* W_proj = (const float*)d_in[3];
    const float* b_proj = (const float*)d_in[4];
    const float* thr    = (const float*)d_in[5];
    const float* leak   = (const float*)d_in[6];
    const float* steep  = (const float*)d_in[7];
    float* out = (float*)d_out;

    gemm_qkv_kernel<<<dim3(NQKV / 64, MROWS / 128), 256>>>(x, W_attn, b_attn);
    lif_attn_kernel<<<dim3(SEQ / 64, NHEAD, BATCH), 256>>>(thr, leak, steep);
    gemm_proj_kernel<<<dim3(EMB / 64, MROWS / 128), 256>>>(W_proj, b_proj, out);
}